// round 15
// baseline (speedup 1.0000x reference)
#include <cuda_runtime.h>
#include <math.h>
#include <stdint.h>

#define D_EMBED 1024
#define S_LEN   2048
#define BATCH   2
#define NHEADS  16
#define DH      64
#define M_TOK   (BATCH * S_LEN)          // 4096

// ---- bf16 hi/lo plane scratch (u32 = packed bf16x2 pair along k/d) ----
__device__ uint32_t g_x_hi   [(size_t)M_TOK * 512];
__device__ uint32_t g_x_lo   [(size_t)M_TOK * 512];
__device__ uint32_t g_win_hi [(size_t)3072 * 512];
__device__ uint32_t g_win_lo [(size_t)3072 * 512];
__device__ uint32_t g_wout_hi[(size_t)1024 * 512];
__device__ uint32_t g_wout_lo[(size_t)1024 * 512];
__device__ uint32_t g_qkv_hi [(size_t)M_TOK * 1536];
__device__ uint32_t g_qkv_lo [(size_t)M_TOK * 1536];
__device__ uint32_t g_attn_hi[(size_t)M_TOK * 512];
__device__ uint32_t g_attn_lo[(size_t)M_TOK * 512];

// ===========================================================================
// Helpers
// ===========================================================================
__device__ __forceinline__ uint32_t smem_u32(const void* p) {
    uint32_t a;
    asm("{ .reg .u64 t; cvta.to.shared.u64 t, %1; cvt.u32.u64 %0, t; }"
        : "=r"(a) : "l"(p));
    return a;
}

__device__ __forceinline__ void mma_bf16(float* d, const uint32_t* a, const uint32_t* b) {
    asm volatile(
        "mma.sync.aligned.m16n8k16.row.col.f32.bf16.bf16.f32 "
        "{%0,%1,%2,%3}, {%4,%5,%6,%7}, {%8,%9}, {%0,%1,%2,%3};\n"
        : "+f"(d[0]), "+f"(d[1]), "+f"(d[2]), "+f"(d[3])
        : "r"(a[0]), "r"(a[1]), "r"(a[2]), "r"(a[3]), "r"(b[0]), "r"(b[1]));
}

__device__ __forceinline__ void ldmx4(uint32_t* r, uint32_t addr) {
    asm volatile(
        "ldmatrix.sync.aligned.m8n8.x4.shared.b16 {%0,%1,%2,%3}, [%4];"
        : "=r"(r[0]), "=r"(r[1]), "=r"(r[2]), "=r"(r[3]) : "r"(addr));
}
__device__ __forceinline__ void ldmx4t(uint32_t* r, uint32_t addr) {
    asm volatile(
        "ldmatrix.sync.aligned.m8n8.x4.trans.shared.b16 {%0,%1,%2,%3}, [%4];"
        : "=r"(r[0]), "=r"(r[1]), "=r"(r[2]), "=r"(r[3]) : "r"(addr));
}

// (f0,f1) -> hi = {bf16(f1)|bf16(f0)}, lo = residuals (f0 in low half)
__device__ __forceinline__ void bf16x3_pack(float f0, float f1,
                                            uint32_t& hi, uint32_t& lo) {
    asm("cvt.rn.bf16x2.f32 %0, %1, %2;" : "=r"(hi) : "f"(f1), "f"(f0));
    float r0 = f0 - __uint_as_float(hi << 16);
    float r1 = f1 - __uint_as_float(hi & 0xFFFF0000u);
    asm("cvt.rn.bf16x2.f32 %0, %1, %2;" : "=r"(lo) : "f"(r1), "f"(r0));
}

__device__ __forceinline__ void cp16(uint32_t sdst, const void* gsrc) {
    asm volatile("cp.async.cg.shared.global [%0], [%1], 16;" :: "r"(sdst), "l"(gsrc));
}
__device__ __forceinline__ void cp_commit() {
    asm volatile("cp.async.commit_group;" ::: "memory");
}
template <int N_>
__device__ __forceinline__ void cp_wait() {
    asm volatile("cp.async.wait_group %0;" :: "n"(N_) : "memory");
}

// ===========================================================================
// Pre-pass 1: fp32 [R][C] -> hi/lo planes [R][C/2]
// ===========================================================================
__global__ __launch_bounds__(256) void split_pairs(
    const float* __restrict__ in, uint32_t* __restrict__ hi,
    uint32_t* __restrict__ lo, int n_pairs)
{
    int i = blockIdx.x * 256 + threadIdx.x;
    if (i < n_pairs) {
        float2 v = reinterpret_cast<const float2*>(in)[i];
        uint32_t h, l;
        bf16x3_pack(v.x, v.y, h, l);
        hi[i] = h; lo[i] = l;
    }
}

// ===========================================================================
// Pre-pass 2: W [K][N] fp32 -> transposed planes [N][K/2]
// ===========================================================================
__global__ __launch_bounds__(256) void split_trans(
    const float* __restrict__ W, uint32_t* __restrict__ bt_hi,
    uint32_t* __restrict__ bt_lo, int K, int N)
{
    __shared__ float s[64][65];
    const int k0 = blockIdx.y * 64, n0 = blockIdx.x * 64;
    const int tid = threadIdx.x;
#pragma unroll
    for (int i = 0; i < 16; i++) {
        int f = tid + i * 256;
        s[f >> 6][f & 63] = W[(size_t)(k0 + (f >> 6)) * N + n0 + (f & 63)];
    }
    __syncthreads();
    const int kp = tid & 31;
    const int Kp = K >> 1;
#pragma unroll
    for (int i = 0; i < 8; i++) {
        int nn = (tid >> 5) + i * 8;
        uint32_t h, l;
        bf16x3_pack(s[2 * kp][nn], s[2 * kp + 1][nn], h, l);
        size_t o = (size_t)(n0 + nn) * Kp + (k0 >> 1) + kp;
        bt_hi[o] = h; bt_lo[o] = l;
    }
}

// ===========================================================================
// Pure-bf16x3 GEMM on pre-split planes.
// 128x64 CTA tile, BK=32 (16 u32), 256 threads (8 warps, 4m x 2n),
// warp tile 32x32, acc 32 regs. launch_bounds(256,3) -> 3 CTAs/SM
// = 24 resident warps.
// Stage layout (u32): AHI 0, ALO 2560, BHI 5120, BLO 6400 (rows stride 20).
// Stage = 7680 u32 = 30720 B; 2 stages = 61440 B/CTA.
// ===========================================================================
#define G_STAGE_U32 7680
#define G_STAGE_B   (G_STAGE_U32 * 4)
#define G_SMEM_BYTES (2 * G_STAGE_B)        // 61440

__global__ __launch_bounds__(256, 3) void gemm_planes(
    const uint32_t* __restrict__ Ahi, const uint32_t* __restrict__ Alo,
    const uint32_t* __restrict__ Bhi, const uint32_t* __restrict__ Blo,
    const float* __restrict__ bias,
    float* __restrict__ Cf, uint32_t* __restrict__ Chi, uint32_t* __restrict__ Clo,
    int M, int N, int K, int write_planes)
{
    extern __shared__ uint32_t s32[];
    const uint32_t sbase = smem_u32(s32);

    const int tid  = threadIdx.x;
    const int lane = tid & 31;
    const int wid  = tid >> 5;
    const int g    = lane >> 2;
    const int tg   = lane & 3;
    const int wm   = wid & 3;        // 0..3  (rows)
    const int wn   = wid >> 2;       // 0..1  (cols)
    const int rowA0 = blockIdx.y * 128;
    const int colB0 = blockIdx.x * 64;
    const int Kp   = K >> 1;

    // loaders: A row = tid>>1, half = tid&1 (8 u32 = 2 cp16); B row = tid>>2
    const int arow = tid >> 1;
    const int aj   = tid & 1;
    const int brow = tid >> 2;
    const int bj   = tid & 3;
    const uint32_t sA_off = (uint32_t)(arow * 20 + aj * 8) * 4;
    const uint32_t sB_off = (uint32_t)(brow * 20 + bj * 4) * 4;
    const uint32_t sA_hi = sbase + sA_off;
    const uint32_t sA_lo = sbase + 2560 * 4 + sA_off;
    const uint32_t sB_hi = sbase + 5120 * 4 + sB_off;
    const uint32_t sB_lo = sbase + 6400 * 4 + sB_off;
    const uint32_t* gA_hi = Ahi + (size_t)(rowA0 + arow) * Kp + aj * 8;
    const uint32_t* gA_lo = Alo + (size_t)(rowA0 + arow) * Kp + aj * 8;
    const uint32_t* gB_hi = Bhi + (size_t)(colB0 + brow) * Kp + bj * 4;
    const uint32_t* gB_lo = Blo + (size_t)(colB0 + brow) * Kp + bj * 4;

    // ldmatrix lane bases (row stride 80 B)
    const uint32_t a_lane = (uint32_t)((wm * 32 + (lane & 15)) * 80 + ((lane >> 4) << 4));
    const uint32_t b_lane = (uint32_t)((wn * 32 + (lane & 15)) * 80 + ((lane >> 4) << 4));
    const uint32_t AHIa = sbase + a_lane;
    const uint32_t ALOa = sbase + 2560 * 4 + a_lane;
    const uint32_t BHIa = sbase + 5120 * 4 + b_lane;
    const uint32_t BLOa = sbase + 6400 * 4 + b_lane;

    float acc[2][4][4];
#pragma unroll
    for (int mt = 0; mt < 2; mt++)
#pragma unroll
        for (int nt = 0; nt < 4; nt++)
#pragma unroll
            for (int i = 0; i < 4; i++) acc[mt][nt][i] = 0.f;

    const int T = K / 32;

    // prologue: stage 0
    cp16(sA_hi, gA_hi);      cp16(sA_hi + 16, gA_hi + 4);
    cp16(sA_lo, gA_lo);      cp16(sA_lo + 16, gA_lo + 4);
    cp16(sB_hi, gB_hi);
    cp16(sB_lo, gB_lo);
    cp_commit();

    for (int t = 0; t < T; t++) {
        if (t + 1 < T) {
            const uint32_t st = (uint32_t)((t + 1) & 1) * G_STAGE_B;
            const int ko = (t + 1) * 16;
            cp16(sA_hi + st, gA_hi + ko);      cp16(sA_hi + st + 16, gA_hi + ko + 4);
            cp16(sA_lo + st, gA_lo + ko);      cp16(sA_lo + st + 16, gA_lo + ko + 4);
            cp16(sB_hi + st, gB_hi + ko);
            cp16(sB_lo + st, gB_lo + ko);
            cp_commit();
            cp_wait<1>();
        } else {
            cp_wait<0>();
        }
        __syncthreads();

        const uint32_t stg = (uint32_t)(t & 1) * G_STAGE_B;
#pragma unroll
        for (int ks = 0; ks < 2; ks++) {
            const uint32_t ko = stg + ks * 32;
            uint32_t aH[2][4], aL[2][4], bfr[4][2], q[4];
            ldmx4(aL[0], ALOa + ko);
            ldmx4(aL[1], ALOa + ko + 1280);
            ldmx4(aH[0], AHIa + ko);
            ldmx4(aH[1], AHIa + ko + 1280);
            ldmx4(q, BHIa + ko);
            bfr[0][0] = q[0]; bfr[1][0] = q[1]; bfr[0][1] = q[2]; bfr[1][1] = q[3];
            ldmx4(q, BHIa + ko + 1280);
            bfr[2][0] = q[0]; bfr[3][0] = q[1]; bfr[2][1] = q[2]; bfr[3][1] = q[3];
#pragma unroll
            for (int mt = 0; mt < 2; mt++)
#pragma unroll
                for (int nt = 0; nt < 4; nt++)
                    mma_bf16(acc[mt][nt], aL[mt], bfr[nt]);
#pragma unroll
            for (int mt = 0; mt < 2; mt++)
#pragma unroll
                for (int nt = 0; nt < 4; nt++)
                    mma_bf16(acc[mt][nt], aH[mt], bfr[nt]);
            ldmx4(q, BLOa + ko);
            bfr[0][0] = q[0]; bfr[1][0] = q[1]; bfr[0][1] = q[2]; bfr[1][1] = q[3];
            ldmx4(q, BLOa + ko + 1280);
            bfr[2][0] = q[0]; bfr[3][0] = q[1]; bfr[2][1] = q[2]; bfr[3][1] = q[3];
#pragma unroll
            for (int mt = 0; mt < 2; mt++)
#pragma unroll
                for (int nt = 0; nt < 4; nt++)
                    mma_bf16(acc[mt][nt], aH[mt], bfr[nt]);
        }
        __syncthreads();
    }

    // ---- epilogue ----
    const int Np = N >> 1;
#pragma unroll
    for (int mt = 0; mt < 2; mt++) {
        const int row = rowA0 + wm * 32 + mt * 16 + g;
#pragma unroll
        for (int nt = 0; nt < 4; nt++) {
            const int col = colB0 + wn * 32 + nt * 8 + 2 * tg;
            const float b0v = bias[col], b1v = bias[col + 1];
            const float c0 = acc[mt][nt][0] + b0v, c1 = acc[mt][nt][1] + b1v;
            const float c2 = acc[mt][nt][2] + b0v, c3 = acc[mt][nt][3] + b1v;
            if (write_planes) {
                uint32_t h, l;
                bf16x3_pack(c0, c1, h, l);
                Chi[(size_t)row * Np + (col >> 1)] = h;
                Clo[(size_t)row * Np + (col >> 1)] = l;
                bf16x3_pack(c2, c3, h, l);
                Chi[(size_t)(row + 8) * Np + (col >> 1)] = h;
                Clo[(size_t)(row + 8) * Np + (col >> 1)] = l;
            } else {
                *reinterpret_cast<float2*>(&Cf[(size_t)row * N + col]) =
                    make_float2(c0, c1);
                *reinterpret_cast<float2*>(&Cf[(size_t)(row + 8) * N + col]) =
                    make_float2(c2, c3);
            }
        }
    }
}

// ===========================================================================
// Flash attention, bf16x3, pre-split planes, cp.async double-buffered K/V.
// (unchanged from Round 12 — 3 CTAs/SM, measured)
// ===========================================================================
#define AT_STAGE_U32 4608
#define AT_SMEM_BYTES 73728

__global__ __launch_bounds__(128, 3) void flash_attn_planes(
    const uint32_t* __restrict__ ghi, const uint32_t* __restrict__ glo,
    uint32_t* __restrict__ ahi, uint32_t* __restrict__ alo)
{
    extern __shared__ uint32_t s32[];
    const uint32_t sb = smem_u32(s32);
    uint32_t* QHI = s32;
    uint32_t* QLO = s32 + 4608;

    const int t    = threadIdx.x;
    const int lane = t & 31;
    const int w    = t >> 5;
    const int g    = lane >> 2;
    const int tg   = lane & 3;
    const int bh   = blockIdx.y;
    const int b    = bh >> 4;
    const int h    = bh & 15;
    const int q0   = blockIdx.x * 128;
    const size_t brow = (size_t)b * S_LEN;
    const int qb   = w * 32;

    const uint32_t QHIa = sb;
    const uint32_t QLOa = sb + 4608 * 4;
    const uint32_t q_lane = (uint32_t)((qb + (lane & 15)) * 144 + ((lane >> 4) << 4));
    const uint32_t k_lane = (uint32_t)((lane & 15) * 144 + ((lane >> 4) << 4));
    const uint32_t v_lane = (uint32_t)(((lane & 7) + ((lane >> 3) & 1) * 8) * 144
                                       + ((lane >> 4) << 4));

    const int pr = t >> 3;
    const int pc = t & 7;

#pragma unroll
    for (int i = 0; i < 8; i++) {
        int f = t + i * 128;
        int r = f >> 3, c = f & 7;
        const size_t src = (brow + q0 + r) * 1536 + h * 32 + c * 4;
        *reinterpret_cast<uint4*>(QHI + r * 36 + c * 4) =
            *reinterpret_cast<const uint4*>(ghi + src);
        *reinterpret_cast<uint4*>(QLO + r * 36 + c * 4) =
            *reinterpret_cast<const uint4*>(glo + src);
    }

    float oacc[2][8][4];
#pragma unroll
    for (int mt = 0; mt < 2; mt++)
#pragma unroll
        for (int nt = 0; nt < 8; nt++)
#pragma unroll
            for (int i = 0; i < 4; i++) oacc[mt][nt][i] = 0.f;
    float lrow[2][2] = {{0.f, 0.f}, {0.f, 0.f}};

#pragma unroll
    for (int i = 0; i < 2; i++) {
        int r = pr + i * 16;
        const size_t srcK = (brow + r) * 1536 + 512 + h * 32 + pc * 4;
        uint32_t d = sb + (9216u + (uint32_t)(r * 36 + pc * 4)) * 4;
        cp16(d,            ghi + srcK);
        cp16(d + 1152 * 4, glo + srcK);
        cp16(d + 2304 * 4, ghi + srcK + 512);
        cp16(d + 3456 * 4, glo + srcK + 512);
    }
    cp_commit();

    for (int kt = 0; kt < S_LEN / 32; kt++) {
        if (kt + 1 < S_LEN / 32) {
            const uint32_t stg_w = 9216u + (uint32_t)((kt + 1) & 1) * AT_STAGE_U32;
#pragma unroll
            for (int i = 0; i < 2; i++) {
                int r = pr + i * 16;
                const size_t srcK = (brow + (kt + 1) * 32 + r) * 1536 + 512
                                    + h * 32 + pc * 4;
                uint32_t d = sb + (stg_w + (uint32_t)(r * 36 + pc * 4)) * 4;
                cp16(d,            ghi + srcK);
                cp16(d + 1152 * 4, glo + srcK);
                cp16(d + 2304 * 4, ghi + srcK + 512);
                cp16(d + 3456 * 4, glo + srcK + 512);
            }
            cp_commit();
            cp_wait<1>();
        } else {
            cp_wait<0>();
        }
        __syncthreads();

        const uint32_t stg = 9216u + (uint32_t)(kt & 1) * AT_STAGE_U32;
        const uint32_t KHIa = sb + stg * 4 + k_lane;
        const uint32_t KLOa = KHIa + 1152 * 4;
        const uint32_t VHIa = sb + stg * 4 + 2304 * 4 + v_lane;
        const uint32_t VLOa = VHIa + 1152 * 4;

        float sacc[2][4][4];
#pragma unroll
        for (int mt = 0; mt < 2; mt++)
#pragma unroll
            for (int nt = 0; nt < 4; nt++)
#pragma unroll
                for (int i = 0; i < 4; i++) sacc[mt][nt][i] = 0.f;

#pragma unroll
        for (int ks = 0; ks < 4; ks++) {
            const uint32_t ko = ks * 32;
            uint32_t aH[2][4], aL[2][4], bfr[4][2], q[4];
            ldmx4(aL[0], QLOa + q_lane + ko);
            ldmx4(aL[1], QLOa + q_lane + ko + 2304);
            ldmx4(aH[0], QHIa + q_lane + ko);
            ldmx4(aH[1], QHIa + q_lane + ko + 2304);
            ldmx4(q, KHIa + ko);
            bfr[0][0] = q[0]; bfr[1][0] = q[1]; bfr[0][1] = q[2]; bfr[1][1] = q[3];
            ldmx4(q, KHIa + ko + 2304);
            bfr[2][0] = q[0]; bfr[3][0] = q[1]; bfr[2][1] = q[2]; bfr[3][1] = q[3];
#pragma unroll
            for (int mt = 0; mt < 2; mt++)
#pragma unroll
                for (int nt = 0; nt < 4; nt++)
                    mma_bf16(sacc[mt][nt], aL[mt], bfr[nt]);
#pragma unroll
            for (int mt = 0; mt < 2; mt++)
#pragma unroll
                for (int nt = 0; nt < 4; nt++)
                    mma_bf16(sacc[mt][nt], aH[mt], bfr[nt]);
            ldmx4(q, KLOa + ko);
            bfr[0][0] = q[0]; bfr[1][0] = q[1]; bfr[0][1] = q[2]; bfr[1][1] = q[3];
            ldmx4(q, KLOa + ko + 2304);
            bfr[2][0] = q[0]; bfr[3][0] = q[1]; bfr[2][1] = q[2]; bfr[3][1] = q[3];
#pragma unroll
            for (int mt = 0; mt < 2; mt++)
#pragma unroll
                for (int nt = 0; nt < 4; nt++)
                    mma_bf16(sacc[mt][nt], aH[mt], bfr[nt]);
        }

        uint32_t phi[2][4][2], plo[2][4][2];
#pragma unroll
        for (int mt = 0; mt < 2; mt++)
#pragma unroll
            for (int nt = 0; nt < 4; nt++) {
                float p0 = __expf(0.125f * sacc[mt][nt][0]);
                float p1 = __expf(0.125f * sacc[mt][nt][1]);
                float p2 = __expf(0.125f * sacc[mt][nt][2]);
                float p3 = __expf(0.125f * sacc[mt][nt][3]);
                lrow[mt][0] += p0 + p1;
                lrow[mt][1] += p2 + p3;
                bf16x3_pack(p0, p1, phi[mt][nt][0], plo[mt][nt][0]);
                bf16x3_pack(p2, p3, phi[mt][nt][1], plo[mt][nt][1]);
            }

#pragma unroll
        for (int s = 0; s < 2; s++) {
            uint32_t vfr[8][2], ah[2][4], al[2][4], q[4];
#pragma unroll
            for (int mt = 0; mt < 2; mt++) {
                ah[mt][0] = phi[mt][2 * s][0];     ah[mt][1] = phi[mt][2 * s][1];
                ah[mt][2] = phi[mt][2 * s + 1][0]; ah[mt][3] = phi[mt][2 * s + 1][1];
                al[mt][0] = plo[mt][2 * s][0];     al[mt][1] = plo[mt][2 * s][1];
                al[mt][2] = plo[mt][2 * s + 1][0]; al[mt][3] = plo[mt][2 * s + 1][1];
            }
#pragma unroll
            for (int nb = 0; nb < 4; nb++) {
                ldmx4t(q, VHIa + s * 2304 + nb * 32);
                vfr[2 * nb][0] = q[0];     vfr[2 * nb][1] = q[1];
                vfr[2 * nb + 1][0] = q[2]; vfr[2 * nb + 1][1] = q[3];
            }
#pragma unroll
            for (int mt = 0; mt < 2; mt++)
#pragma unroll
                for (int nt = 0; nt < 8; nt++)
                    mma_bf16(oacc[mt][nt], al[mt], vfr[nt]);
#pragma unroll
            for (int mt = 0; mt < 2; mt++)
#pragma unroll
                for (int nt = 0; nt < 8; nt++)
                    mma_bf16(oacc[mt][nt], ah[mt], vfr[nt]);
#pragma unroll
            for (int nb = 0; nb < 4; nb++) {
                ldmx4t(q, VLOa + s * 2304 + nb * 32);
                vfr[2 * nb][0] = q[0];     vfr[2 * nb][1] = q[1];
                vfr[2 * nb + 1][0] = q[2]; vfr[2 * nb + 1][1] = q[3];
            }
#pragma unroll
            for (int mt = 0; mt < 2; mt++)
#pragma unroll
                for (int nt = 0; nt < 8; nt++)
                    mma_bf16(oacc[mt][nt], ah[mt], vfr[nt]);
        }
        __syncthreads();
    }

#pragma unroll
    for (int mt = 0; mt < 2; mt++)
#pragma unroll
        for (int hf = 0; hf < 2; hf++) {
            float v = lrow[mt][hf];
            v += __shfl_xor_sync(0xffffffff, v, 1);
            v += __shfl_xor_sync(0xffffffff, v, 2);
            lrow[mt][hf] = 1.0f / v;
        }

#pragma unroll
    for (int mt = 0; mt < 2; mt++) {
        const size_t r0 = brow + q0 + qb + mt * 16 + g;
#pragma unroll
        for (int nt = 0; nt < 8; nt++) {
            const int cp = h * 32 + nt * 4 + tg;
            uint32_t hh, ll;
            bf16x3_pack(oacc[mt][nt][0] * lrow[mt][0],
                        oacc[mt][nt][1] * lrow[mt][0], hh, ll);
            ahi[r0 * 512 + cp] = hh; alo[r0 * 512 + cp] = ll;
            bf16x3_pack(oacc[mt][nt][2] * lrow[mt][1],
                        oacc[mt][nt][3] * lrow[mt][1], hh, ll);
            ahi[(r0 + 8) * 512 + cp] = hh; alo[(r0 + 8) * 512 + cp] = ll;
        }
    }
}

// ===========================================================================
extern "C" void kernel_launch(void* const* d_in, const int* in_sizes, int n_in,
                              void* d_out, int out_size)
{
    const float* x     = (const float*)d_in[0];
    const float* W_in  = (const float*)d_in[1];
    const float* b_in  = (const float*)d_in[2];
    const float* W_out = (const float*)d_in[3];
    const float* b_out = (const float*)d_in[4];
    float* out = (float*)d_out;

    uint32_t *xh, *xl, *wih, *wil, *woh, *wol, *qh, *ql, *ah, *al;
    cudaGetSymbolAddress((void**)&xh,  g_x_hi);
    cudaGetSymbolAddress((void**)&xl,  g_x_lo);
    cudaGetSymbolAddress((void**)&wih, g_win_hi);
    cudaGetSymbolAddress((void**)&wil, g_win_lo);
    cudaGetSymbolAddress((void**)&woh, g_wout_hi);
    cudaGetSymbolAddress((void**)&wol, g_wout_lo);
    cudaGetSymbolAddress((void**)&qh,  g_qkv_hi);
    cudaGetSymbolAddress((void**)&ql,  g_qkv_lo);
    cudaGetSymbolAddress((void**)&ah,  g_attn_hi);
    cudaGetSymbolAddress((void**)&al,  g_attn_lo);

    const int M = M_TOK;
    const int D = D_EMBED;

    cudaFuncSetAttribute(gemm_planes,
                         cudaFuncAttributeMaxDynamicSharedMemorySize, G_SMEM_BYTES);
    cudaFuncSetAttribute(flash_attn_planes,
                         cudaFuncAttributeMaxDynamicSharedMemorySize, AT_SMEM_BYTES);

    // 0) pre-split inputs
    split_pairs<<<(M * D / 2 + 255) / 256, 256>>>(x, xh, xl, M * D / 2);
    split_trans<<<dim3(3 * D / 64, D / 64), 256>>>(W_in, wih, wil, D, 3 * D);
    split_trans<<<dim3(D / 64, D / 64), 256>>>(W_out, woh, wol, D, D);

    // 1) QKV projection -> qkv planes
    {
        dim3 grid(3 * D / 64, M / 128);
        gemm_planes<<<grid, 256, G_SMEM_BYTES>>>(
            xh, xl, wih, wil, b_in, nullptr, qh, ql, M, 3 * D, D, 1);
    }
    // 2) attention -> attn planes
    {
        dim3 grid(S_LEN / 128, BATCH * NHEADS);
        flash_attn_planes<<<grid, 128, AT_SMEM_BYTES>>>(qh, ql, ah, al);
    }
    // 3) output projection -> fp32 out
    {
        dim3 grid(D / 64, M / 128);
        gemm_planes<<<grid, 256, G_SMEM_BYTES>>>(
            ah, al, woh, wol, b_out, out, nullptr, nullptr, M, D, D, 0);
    }
}

// round 16
// speedup vs baseline: 1.0230x; 1.0230x over previous
#include <cuda_runtime.h>
#include <math.h>
#include <stdint.h>

#define D_EMBED 1024
#define S_LEN   2048
#define BATCH   2
#define NHEADS  16
#define DH      64
#define M_TOK   (BATCH * S_LEN)          // 4096

// ---- bf16 hi/lo plane scratch (u32 = packed bf16x2 pair along k/d) ----
__device__ uint32_t g_x_hi   [(size_t)M_TOK * 512];
__device__ uint32_t g_x_lo   [(size_t)M_TOK * 512];
__device__ uint32_t g_win_hi [(size_t)3072 * 512];
__device__ uint32_t g_win_lo [(size_t)3072 * 512];
__device__ uint32_t g_wout_hi[(size_t)1024 * 512];
__device__ uint32_t g_wout_lo[(size_t)1024 * 512];
__device__ uint32_t g_qkv_hi [(size_t)M_TOK * 1536];
__device__ uint32_t g_qkv_lo [(size_t)M_TOK * 1536];
__device__ uint32_t g_attn_hi[(size_t)M_TOK * 512];
__device__ uint32_t g_attn_lo[(size_t)M_TOK * 512];

// ===========================================================================
// Helpers
// ===========================================================================
__device__ __forceinline__ uint32_t smem_u32(const void* p) {
    uint32_t a;
    asm("{ .reg .u64 t; cvta.to.shared.u64 t, %1; cvt.u32.u64 %0, t; }"
        : "=r"(a) : "l"(p));
    return a;
}

__device__ __forceinline__ void mma_bf16(float* d, const uint32_t* a, const uint32_t* b) {
    asm volatile(
        "mma.sync.aligned.m16n8k16.row.col.f32.bf16.bf16.f32 "
        "{%0,%1,%2,%3}, {%4,%5,%6,%7}, {%8,%9}, {%0,%1,%2,%3};\n"
        : "+f"(d[0]), "+f"(d[1]), "+f"(d[2]), "+f"(d[3])
        : "r"(a[0]), "r"(a[1]), "r"(a[2]), "r"(a[3]), "r"(b[0]), "r"(b[1]));
}

__device__ __forceinline__ void ldmx4(uint32_t* r, uint32_t addr) {
    asm volatile(
        "ldmatrix.sync.aligned.m8n8.x4.shared.b16 {%0,%1,%2,%3}, [%4];"
        : "=r"(r[0]), "=r"(r[1]), "=r"(r[2]), "=r"(r[3]) : "r"(addr));
}
__device__ __forceinline__ void ldmx4t(uint32_t* r, uint32_t addr) {
    asm volatile(
        "ldmatrix.sync.aligned.m8n8.x4.trans.shared.b16 {%0,%1,%2,%3}, [%4];"
        : "=r"(r[0]), "=r"(r[1]), "=r"(r[2]), "=r"(r[3]) : "r"(addr));
}

// (f0,f1) -> hi = {bf16(f1)|bf16(f0)}, lo = residuals (f0 in low half)
__device__ __forceinline__ void bf16x3_pack(float f0, float f1,
                                            uint32_t& hi, uint32_t& lo) {
    asm("cvt.rn.bf16x2.f32 %0, %1, %2;" : "=r"(hi) : "f"(f1), "f"(f0));
    float r0 = f0 - __uint_as_float(hi << 16);
    float r1 = f1 - __uint_as_float(hi & 0xFFFF0000u);
    asm("cvt.rn.bf16x2.f32 %0, %1, %2;" : "=r"(lo) : "f"(r1), "f"(r0));
}

__device__ __forceinline__ void cp16(uint32_t sdst, const void* gsrc) {
    asm volatile("cp.async.cg.shared.global [%0], [%1], 16;" :: "r"(sdst), "l"(gsrc));
}
__device__ __forceinline__ void cp_commit() {
    asm volatile("cp.async.commit_group;" ::: "memory");
}
template <int N_>
__device__ __forceinline__ void cp_wait() {
    asm volatile("cp.async.wait_group %0;" :: "n"(N_) : "memory");
}

// ===========================================================================
// Pre-pass 1: fp32 [R][C] -> hi/lo planes [R][C/2]
// ===========================================================================
__global__ __launch_bounds__(256) void split_pairs(
    const float* __restrict__ in, uint32_t* __restrict__ hi,
    uint32_t* __restrict__ lo, int n_pairs)
{
    int i = blockIdx.x * 256 + threadIdx.x;
    if (i < n_pairs) {
        float2 v = reinterpret_cast<const float2*>(in)[i];
        uint32_t h, l;
        bf16x3_pack(v.x, v.y, h, l);
        hi[i] = h; lo[i] = l;
    }
}

// ===========================================================================
// Pre-pass 2: W [K][N] fp32 -> transposed planes [N][K/2]
// ===========================================================================
__global__ __launch_bounds__(256) void split_trans(
    const float* __restrict__ W, uint32_t* __restrict__ bt_hi,
    uint32_t* __restrict__ bt_lo, int K, int N)
{
    __shared__ float s[64][65];
    const int k0 = blockIdx.y * 64, n0 = blockIdx.x * 64;
    const int tid = threadIdx.x;
#pragma unroll
    for (int i = 0; i < 16; i++) {
        int f = tid + i * 256;
        s[f >> 6][f & 63] = W[(size_t)(k0 + (f >> 6)) * N + n0 + (f & 63)];
    }
    __syncthreads();
    const int kp = tid & 31;
    const int Kp = K >> 1;
#pragma unroll
    for (int i = 0; i < 8; i++) {
        int nn = (tid >> 5) + i * 8;
        uint32_t h, l;
        bf16x3_pack(s[2 * kp][nn], s[2 * kp + 1][nn], h, l);
        size_t o = (size_t)(n0 + nn) * Kp + (k0 >> 1) + kp;
        bt_hi[o] = h; bt_lo[o] = l;
    }
}

// ===========================================================================
// Pure-bf16x3 GEMM on pre-split planes, 3-stage cp.async pipeline.
// 128x128 CTA tile, BK=32 (16 u32), 512 threads (16 warps, 4m x 4n).
// ONE barrier per tile (3-stage ring makes the trailing barrier redundant:
// iter t writes stage (t+2)%3 = (t-1)%3, whose readers finished before the
// top-of-t barrier). Both ksteps' fragments hoisted ahead of all 48 MMAs
// so ldmatrix latency hides inside the MMA stream.
// Stage layout (u32): AHI 0, ALO 2560, BHI 5120, BLO 7680 (rows stride 20).
// ===========================================================================
#define G_STAGE_U32 10240
#define G_STAGE_B   (G_STAGE_U32 * 4)
#define G_SMEM_BYTES (3 * G_STAGE_B)        // 122880

__global__ __launch_bounds__(512) void gemm_planes(
    const uint32_t* __restrict__ Ahi, const uint32_t* __restrict__ Alo,
    const uint32_t* __restrict__ Bhi, const uint32_t* __restrict__ Blo,
    const float* __restrict__ bias,
    float* __restrict__ Cf, uint32_t* __restrict__ Chi, uint32_t* __restrict__ Clo,
    int M, int N, int K, int write_planes)
{
    extern __shared__ uint32_t s32[];
    const uint32_t sbase = smem_u32(s32);

    const int tid  = threadIdx.x;
    const int lane = tid & 31;
    const int wid  = tid >> 5;
    const int g    = lane >> 2;
    const int tg   = lane & 3;
    const int wm   = wid & 3;
    const int wn   = wid >> 2;
    const int rowA0 = blockIdx.y * 128;
    const int colB0 = blockIdx.x * 128;
    const int Kp   = K >> 1;

    const int lrow = tid >> 2;
    const int lj   = tid & 3;
    const uint32_t s_off = (uint32_t)(lrow * 20 + lj * 4) * 4;
    const uint32_t sA_hi = sbase + s_off;
    const uint32_t sA_lo = sbase + 2560 * 4 + s_off;
    const uint32_t sB_hi = sbase + 5120 * 4 + s_off;
    const uint32_t sB_lo = sbase + 7680 * 4 + s_off;
    const uint32_t* gA_hi = Ahi + (size_t)(rowA0 + lrow) * Kp + lj * 4;
    const uint32_t* gA_lo = Alo + (size_t)(rowA0 + lrow) * Kp + lj * 4;
    const uint32_t* gB_hi = Bhi + (size_t)(colB0 + lrow) * Kp + lj * 4;
    const uint32_t* gB_lo = Blo + (size_t)(colB0 + lrow) * Kp + lj * 4;

    const uint32_t a_lane = (uint32_t)((wm * 32 + (lane & 15)) * 80 + ((lane >> 4) << 4));
    const uint32_t b_lane = (uint32_t)((wn * 32 + (lane & 15)) * 80 + ((lane >> 4) << 4));
    const uint32_t AHIa = sbase + a_lane;
    const uint32_t ALOa = sbase + 2560 * 4 + a_lane;
    const uint32_t BHIa = sbase + 5120 * 4 + b_lane;
    const uint32_t BLOa = sbase + 7680 * 4 + b_lane;

    float acc[2][4][4];
#pragma unroll
    for (int mt = 0; mt < 2; mt++)
#pragma unroll
        for (int nt = 0; nt < 4; nt++)
#pragma unroll
            for (int i = 0; i < 4; i++) acc[mt][nt][i] = 0.f;

    const int T = K / 32;

    // prologue: stages 0, 1
#pragma unroll
    for (int p = 0; p < 2; p++) {
        const uint32_t st = (uint32_t)p * G_STAGE_B;
        const int ko = p * 16;
        cp16(sA_hi + st, gA_hi + ko); cp16(sA_lo + st, gA_lo + ko);
        cp16(sB_hi + st, gB_hi + ko); cp16(sB_lo + st, gB_lo + ko);
        cp_commit();
    }

    int s_rd = 0, s_wr = 2;
    for (int t = 0; t < T; t++) {
        cp_wait<1>();
        __syncthreads();   // single barrier per tile (3-stage ring)

        if (t + 2 < T) {
            const uint32_t st = (uint32_t)s_wr * G_STAGE_B;
            const int ko = (t + 2) * 16;
            cp16(sA_hi + st, gA_hi + ko); cp16(sA_lo + st, gA_lo + ko);
            cp16(sB_hi + st, gB_hi + ko); cp16(sB_lo + st, gB_lo + ko);
        }
        cp_commit();

        const uint32_t stg = (uint32_t)s_rd * G_STAGE_B;

        // ---- hoist ALL fragment loads (both ksteps) ----
        uint32_t aL[2][2][4], aH[2][2][4], bH[2][4][2], bL[2][4][2], q[4];
#pragma unroll
        for (int ks = 0; ks < 2; ks++) {
            const uint32_t ko = stg + ks * 32;
            ldmx4(aL[ks][0], ALOa + ko);
            ldmx4(aL[ks][1], ALOa + ko + 1280);
            ldmx4(aH[ks][0], AHIa + ko);
            ldmx4(aH[ks][1], AHIa + ko + 1280);
            ldmx4(q, BHIa + ko);
            bH[ks][0][0] = q[0]; bH[ks][1][0] = q[1];
            bH[ks][0][1] = q[2]; bH[ks][1][1] = q[3];
            ldmx4(q, BHIa + ko + 1280);
            bH[ks][2][0] = q[0]; bH[ks][3][0] = q[1];
            bH[ks][2][1] = q[2]; bH[ks][3][1] = q[3];
            ldmx4(q, BLOa + ko);
            bL[ks][0][0] = q[0]; bL[ks][1][0] = q[1];
            bL[ks][0][1] = q[2]; bL[ks][1][1] = q[3];
            ldmx4(q, BLOa + ko + 1280);
            bL[ks][2][0] = q[0]; bL[ks][3][0] = q[1];
            bL[ks][2][1] = q[2]; bL[ks][3][1] = q[3];
        }

        // ---- 48 MMAs, no interleaved loads ----
#pragma unroll
        for (int ks = 0; ks < 2; ks++) {
#pragma unroll
            for (int mt = 0; mt < 2; mt++)
#pragma unroll
                for (int nt = 0; nt < 4; nt++)
                    mma_bf16(acc[mt][nt], aL[ks][mt], bH[ks][nt]);
#pragma unroll
            for (int mt = 0; mt < 2; mt++)
#pragma unroll
                for (int nt = 0; nt < 4; nt++)
                    mma_bf16(acc[mt][nt], aH[ks][mt], bH[ks][nt]);
#pragma unroll
            for (int mt = 0; mt < 2; mt++)
#pragma unroll
                for (int nt = 0; nt < 4; nt++)
                    mma_bf16(acc[mt][nt], aH[ks][mt], bL[ks][nt]);
        }

        s_rd = (s_rd == 2) ? 0 : s_rd + 1;
        s_wr = (s_wr == 2) ? 0 : s_wr + 1;
    }

    // ---- epilogue ----
    const int Np = N >> 1;
#pragma unroll
    for (int mt = 0; mt < 2; mt++) {
        const int row = rowA0 + wm * 32 + mt * 16 + g;
#pragma unroll
        for (int nt = 0; nt < 4; nt++) {
            const int col = colB0 + wn * 32 + nt * 8 + 2 * tg;
            const float b0v = bias[col], b1v = bias[col + 1];
            const float c0 = acc[mt][nt][0] + b0v, c1 = acc[mt][nt][1] + b1v;
            const float c2 = acc[mt][nt][2] + b0v, c3 = acc[mt][nt][3] + b1v;
            if (write_planes) {
                uint32_t h, l;
                bf16x3_pack(c0, c1, h, l);
                Chi[(size_t)row * Np + (col >> 1)] = h;
                Clo[(size_t)row * Np + (col >> 1)] = l;
                bf16x3_pack(c2, c3, h, l);
                Chi[(size_t)(row + 8) * Np + (col >> 1)] = h;
                Clo[(size_t)(row + 8) * Np + (col >> 1)] = l;
            } else {
                *reinterpret_cast<float2*>(&Cf[(size_t)row * N + col]) =
                    make_float2(c0, c1);
                *reinterpret_cast<float2*>(&Cf[(size_t)(row + 8) * N + col]) =
                    make_float2(c2, c3);
            }
        }
    }
}

// ===========================================================================
// Flash attention, bf16x3, pre-split planes, cp.async double-buffered K/V.
// (unchanged from Round 12 — best measured)
// ===========================================================================
#define AT_STAGE_U32 4608
#define AT_SMEM_BYTES 73728

__global__ __launch_bounds__(128, 3) void flash_attn_planes(
    const uint32_t* __restrict__ ghi, const uint32_t* __restrict__ glo,
    uint32_t* __restrict__ ahi, uint32_t* __restrict__ alo)
{
    extern __shared__ uint32_t s32[];
    const uint32_t sb = smem_u32(s32);
    uint32_t* QHI = s32;
    uint32_t* QLO = s32 + 4608;

    const int t    = threadIdx.x;
    const int lane = t & 31;
    const int w    = t >> 5;
    const int g    = lane >> 2;
    const int tg   = lane & 3;
    const int bh   = blockIdx.y;
    const int b    = bh >> 4;
    const int h    = bh & 15;
    const int q0   = blockIdx.x * 128;
    const size_t brow = (size_t)b * S_LEN;
    const int qb   = w * 32;

    const uint32_t QHIa = sb;
    const uint32_t QLOa = sb + 4608 * 4;
    const uint32_t q_lane = (uint32_t)((qb + (lane & 15)) * 144 + ((lane >> 4) << 4));
    const uint32_t k_lane = (uint32_t)((lane & 15) * 144 + ((lane >> 4) << 4));
    const uint32_t v_lane = (uint32_t)(((lane & 7) + ((lane >> 3) & 1) * 8) * 144
                                       + ((lane >> 4) << 4));

    const int pr = t >> 3;
    const int pc = t & 7;

#pragma unroll
    for (int i = 0; i < 8; i++) {
        int f = t + i * 128;
        int r = f >> 3, c = f & 7;
        const size_t src = (brow + q0 + r) * 1536 + h * 32 + c * 4;
        *reinterpret_cast<uint4*>(QHI + r * 36 + c * 4) =
            *reinterpret_cast<const uint4*>(ghi + src);
        *reinterpret_cast<uint4*>(QLO + r * 36 + c * 4) =
            *reinterpret_cast<const uint4*>(glo + src);
    }

    float oacc[2][8][4];
#pragma unroll
    for (int mt = 0; mt < 2; mt++)
#pragma unroll
        for (int nt = 0; nt < 8; nt++)
#pragma unroll
            for (int i = 0; i < 4; i++) oacc[mt][nt][i] = 0.f;
    float lrow[2][2] = {{0.f, 0.f}, {0.f, 0.f}};

#pragma unroll
    for (int i = 0; i < 2; i++) {
        int r = pr + i * 16;
        const size_t srcK = (brow + r) * 1536 + 512 + h * 32 + pc * 4;
        uint32_t d = sb + (9216u + (uint32_t)(r * 36 + pc * 4)) * 4;
        cp16(d,            ghi + srcK);
        cp16(d + 1152 * 4, glo + srcK);
        cp16(d + 2304 * 4, ghi + srcK + 512);
        cp16(d + 3456 * 4, glo + srcK + 512);
    }
    cp_commit();

    for (int kt = 0; kt < S_LEN / 32; kt++) {
        if (kt + 1 < S_LEN / 32) {
            const uint32_t stg_w = 9216u + (uint32_t)((kt + 1) & 1) * AT_STAGE_U32;
#pragma unroll
            for (int i = 0; i < 2; i++) {
                int r = pr + i * 16;
                const size_t srcK = (brow + (kt + 1) * 32 + r) * 1536 + 512
                                    + h * 32 + pc * 4;
                uint32_t d = sb + (stg_w + (uint32_t)(r * 36 + pc * 4)) * 4;
                cp16(d,            ghi + srcK);
                cp16(d + 1152 * 4, glo + srcK);
                cp16(d + 2304 * 4, ghi + srcK + 512);
                cp16(d + 3456 * 4, glo + srcK + 512);
            }
            cp_commit();
            cp_wait<1>();
        } else {
            cp_wait<0>();
        }
        __syncthreads();

        const uint32_t stg = 9216u + (uint32_t)(kt & 1) * AT_STAGE_U32;
        const uint32_t KHIa = sb + stg * 4 + k_lane;
        const uint32_t KLOa = KHIa + 1152 * 4;
        const uint32_t VHIa = sb + stg * 4 + 2304 * 4 + v_lane;
        const uint32_t VLOa = VHIa + 1152 * 4;

        float sacc[2][4][4];
#pragma unroll
        for (int mt = 0; mt < 2; mt++)
#pragma unroll
            for (int nt = 0; nt < 4; nt++)
#pragma unroll
                for (int i = 0; i < 4; i++) sacc[mt][nt][i] = 0.f;

#pragma unroll
        for (int ks = 0; ks < 4; ks++) {
            const uint32_t ko = ks * 32;
            uint32_t aH[2][4], aL[2][4], bfr[4][2], q[4];
            ldmx4(aL[0], QLOa + q_lane + ko);
            ldmx4(aL[1], QLOa + q_lane + ko + 2304);
            ldmx4(aH[0], QHIa + q_lane + ko);
            ldmx4(aH[1], QHIa + q_lane + ko + 2304);
            ldmx4(q, KHIa + ko);
            bfr[0][0] = q[0]; bfr[1][0] = q[1]; bfr[0][1] = q[2]; bfr[1][1] = q[3];
            ldmx4(q, KHIa + ko + 2304);
            bfr[2][0] = q[0]; bfr[3][0] = q[1]; bfr[2][1] = q[2]; bfr[3][1] = q[3];
#pragma unroll
            for (int mt = 0; mt < 2; mt++)
#pragma unroll
                for (int nt = 0; nt < 4; nt++)
                    mma_bf16(sacc[mt][nt], aL[mt], bfr[nt]);
#pragma unroll
            for (int mt = 0; mt < 2; mt++)
#pragma unroll
                for (int nt = 0; nt < 4; nt++)
                    mma_bf16(sacc[mt][nt], aH[mt], bfr[nt]);
            ldmx4(q, KLOa + ko);
            bfr[0][0] = q[0]; bfr[1][0] = q[1]; bfr[0][1] = q[2]; bfr[1][1] = q[3];
            ldmx4(q, KLOa + ko + 2304);
            bfr[2][0] = q[0]; bfr[3][0] = q[1]; bfr[2][1] = q[2]; bfr[3][1] = q[3];
#pragma unroll
            for (int mt = 0; mt < 2; mt++)
#pragma unroll
                for (int nt = 0; nt < 4; nt++)
                    mma_bf16(sacc[mt][nt], aH[mt], bfr[nt]);
        }

        uint32_t phi[2][4][2], plo[2][4][2];
#pragma unroll
        for (int mt = 0; mt < 2; mt++)
#pragma unroll
            for (int nt = 0; nt < 4; nt++) {
                float p0 = __expf(0.125f * sacc[mt][nt][0]);
                float p1 = __expf(0.125f * sacc[mt][nt][1]);
                float p2 = __expf(0.125f * sacc[mt][nt][2]);
                float p3 = __expf(0.125f * sacc[mt][nt][3]);
                lrow[mt][0] += p0 + p1;
                lrow[mt][1] += p2 + p3;
                bf16x3_pack(p0, p1, phi[mt][nt][0], plo[mt][nt][0]);
                bf16x3_pack(p2, p3, phi[mt][nt][1], plo[mt][nt][1]);
            }

#pragma unroll
        for (int s = 0; s < 2; s++) {
            uint32_t vfr[8][2], ah[2][4], al[2][4], q[4];
#pragma unroll
            for (int mt = 0; mt < 2; mt++) {
                ah[mt][0] = phi[mt][2 * s][0];     ah[mt][1] = phi[mt][2 * s][1];
                ah[mt][2] = phi[mt][2 * s + 1][0]; ah[mt][3] = phi[mt][2 * s + 1][1];
                al[mt][0] = plo[mt][2 * s][0];     al[mt][1] = plo[mt][2 * s][1];
                al[mt][2] = plo[mt][2 * s + 1][0]; al[mt][3] = plo[mt][2 * s + 1][1];
            }
#pragma unroll
            for (int nb = 0; nb < 4; nb++) {
                ldmx4t(q, VHIa + s * 2304 + nb * 32);
                vfr[2 * nb][0] = q[0];     vfr[2 * nb][1] = q[1];
                vfr[2 * nb + 1][0] = q[2]; vfr[2 * nb + 1][1] = q[3];
            }
#pragma unroll
            for (int mt = 0; mt < 2; mt++)
#pragma unroll
                for (int nt = 0; nt < 8; nt++)
                    mma_bf16(oacc[mt][nt], al[mt], vfr[nt]);
#pragma unroll
            for (int mt = 0; mt < 2; mt++)
#pragma unroll
                for (int nt = 0; nt < 8; nt++)
                    mma_bf16(oacc[mt][nt], ah[mt], vfr[nt]);
#pragma unroll
            for (int nb = 0; nb < 4; nb++) {
                ldmx4t(q, VLOa + s * 2304 + nb * 32);
                vfr[2 * nb][0] = q[0];     vfr[2 * nb][1] = q[1];
                vfr[2 * nb + 1][0] = q[2]; vfr[2 * nb + 1][1] = q[3];
            }
#pragma unroll
            for (int mt = 0; mt < 2; mt++)
#pragma unroll
                for (int nt = 0; nt < 8; nt++)
                    mma_bf16(oacc[mt][nt], ah[mt], vfr[nt]);
        }
        __syncthreads();
    }

#pragma unroll
    for (int mt = 0; mt < 2; mt++)
#pragma unroll
        for (int hf = 0; hf < 2; hf++) {
            float v = lrow[mt][hf];
            v += __shfl_xor_sync(0xffffffff, v, 1);
            v += __shfl_xor_sync(0xffffffff, v, 2);
            lrow[mt][hf] = 1.0f / v;
        }

#pragma unroll
    for (int mt = 0; mt < 2; mt++) {
        const size_t r0 = brow + q0 + qb + mt * 16 + g;
#pragma unroll
        for (int nt = 0; nt < 8; nt++) {
            const int cp = h * 32 + nt * 4 + tg;
            uint32_t hh, ll;
            bf16x3_pack(oacc[mt][nt][0] * lrow[mt][0],
                        oacc[mt][nt][1] * lrow[mt][0], hh, ll);
            ahi[r0 * 512 + cp] = hh; alo[r0 * 512 + cp] = ll;
            bf16x3_pack(oacc[mt][nt][2] * lrow[mt][1],
                        oacc[mt][nt][3] * lrow[mt][1], hh, ll);
            ahi[(r0 + 8) * 512 + cp] = hh; alo[(r0 + 8) * 512 + cp] = ll;
        }
    }
}

// ===========================================================================
extern "C" void kernel_launch(void* const* d_in, const int* in_sizes, int n_in,
                              void* d_out, int out_size)
{
    const float* x     = (const float*)d_in[0];
    const float* W_in  = (const float*)d_in[1];
    const float* b_in  = (const float*)d_in[2];
    const float* W_out = (const float*)d_in[3];
    const float* b_out = (const float*)d_in[4];
    float* out = (float*)d_out;

    uint32_t *xh, *xl, *wih, *wil, *woh, *wol, *qh, *ql, *ah, *al;
    cudaGetSymbolAddress((void**)&xh,  g_x_hi);
    cudaGetSymbolAddress((void**)&xl,  g_x_lo);
    cudaGetSymbolAddress((void**)&wih, g_win_hi);
    cudaGetSymbolAddress((void**)&wil, g_win_lo);
    cudaGetSymbolAddress((void**)&woh, g_wout_hi);
    cudaGetSymbolAddress((void**)&wol, g_wout_lo);
    cudaGetSymbolAddress((void**)&qh,  g_qkv_hi);
    cudaGetSymbolAddress((void**)&ql,  g_qkv_lo);
    cudaGetSymbolAddress((void**)&ah,  g_attn_hi);
    cudaGetSymbolAddress((void**)&al,  g_attn_lo);

    const int M = M_TOK;
    const int D = D_EMBED;

    cudaFuncSetAttribute(gemm_planes,
                         cudaFuncAttributeMaxDynamicSharedMemorySize, G_SMEM_BYTES);
    cudaFuncSetAttribute(flash_attn_planes,
                         cudaFuncAttributeMaxDynamicSharedMemorySize, AT_SMEM_BYTES);

    // 0) pre-split inputs
    split_pairs<<<(M * D / 2 + 255) / 256, 256>>>(x, xh, xl, M * D / 2);
    split_trans<<<dim3(3 * D / 64, D / 64), 256>>>(W_in, wih, wil, D, 3 * D);
    split_trans<<<dim3(D / 64, D / 64), 256>>>(W_out, woh, wol, D, D);

    // 1) QKV projection -> qkv planes
    {
        dim3 grid(3 * D / 128, M / 128);
        gemm_planes<<<grid, 512, G_SMEM_BYTES>>>(
            xh, xl, wih, wil, b_in, nullptr, qh, ql, M, 3 * D, D, 1);
    }
    // 2) attention -> attn planes
    {
        dim3 grid(S_LEN / 128, BATCH * NHEADS);
        flash_attn_planes<<<grid, 128, AT_SMEM_BYTES>>>(qh, ql, ah, al);
    }
    // 3) output projection -> fp32 out
    {
        dim3 grid(D / 128, M / 128);
        gemm_planes<<<grid, 512, G_SMEM_BYTES>>>(
            ah, al, woh, wol, b_out, out, nullptr, nullptr, M, D, D, 0);
    }
}

// round 17
// speedup vs baseline: 1.6141x; 1.5779x over previous
#include <cuda_runtime.h>
#include <cuda_fp16.h>
#include <math.h>
#include <stdint.h>

#define D_EMBED 1024
#define S_LEN   2048
#define BATCH   2
#define NHEADS  16
#define DH      64
#define M_TOK   (BATCH * S_LEN)          // 4096

// ---- fp16 plane scratch (u32 = packed f16x2 pair along k/d) ----
__device__ uint32_t g_x_hi  [(size_t)M_TOK * 512];
__device__ uint32_t g_x_lo  [(size_t)M_TOK * 512];
__device__ uint32_t g_win   [(size_t)3072 * 512];   // W_in^T  single (rounded)
__device__ uint32_t g_wout  [(size_t)1024 * 512];   // W_out^T single (rounded)
__device__ uint32_t g_qkv   [(size_t)M_TOK * 1536]; // qkv single fp16 plane
__device__ uint32_t g_attn_hi[(size_t)M_TOK * 512];
__device__ uint32_t g_attn_lo[(size_t)M_TOK * 512];

// ===========================================================================
// Helpers
// ===========================================================================
__device__ __forceinline__ uint32_t smem_u32(const void* p) {
    uint32_t a;
    asm("{ .reg .u64 t; cvta.to.shared.u64 t, %1; cvt.u32.u64 %0, t; }"
        : "=r"(a) : "l"(p));
    return a;
}

// fp16 m16n8k16 mma: D += A(16x16 row) * B(16x8 col), fp32 accum
__device__ __forceinline__ void mma_f16(float* d, const uint32_t* a, const uint32_t* b) {
    asm volatile(
        "mma.sync.aligned.m16n8k16.row.col.f32.f16.f16.f32 "
        "{%0,%1,%2,%3}, {%4,%5,%6,%7}, {%8,%9}, {%0,%1,%2,%3};\n"
        : "+f"(d[0]), "+f"(d[1]), "+f"(d[2]), "+f"(d[3])
        : "r"(a[0]), "r"(a[1]), "r"(a[2]), "r"(a[3]), "r"(b[0]), "r"(b[1]));
}

__device__ __forceinline__ void ldmx4(uint32_t* r, uint32_t addr) {
    asm volatile(
        "ldmatrix.sync.aligned.m8n8.x4.shared.b16 {%0,%1,%2,%3}, [%4];"
        : "=r"(r[0]), "=r"(r[1]), "=r"(r[2]), "=r"(r[3]) : "r"(addr));
}
__device__ __forceinline__ void ldmx4t(uint32_t* r, uint32_t addr) {
    asm volatile(
        "ldmatrix.sync.aligned.m8n8.x4.trans.shared.b16 {%0,%1,%2,%3}, [%4];"
        : "=r"(r[0]), "=r"(r[1]), "=r"(r[2]), "=r"(r[3]) : "r"(addr));
}

// pack (f0,f1) as f16x2, f0 in low half (smaller-k element)
__device__ __forceinline__ uint32_t f16x2_pack(float f0, float f1) {
    __half2 h = __floats2half2_rn(f0, f1);
    return *reinterpret_cast<uint32_t*>(&h);
}
// split (f0,f1) -> hi = f16x2, lo = f16x2 of residuals
__device__ __forceinline__ void f16x3_split(float f0, float f1,
                                            uint32_t& hi, uint32_t& lo) {
    __half2 h = __floats2half2_rn(f0, f1);
    float2 bk = __half22float2(h);
    hi = *reinterpret_cast<uint32_t*>(&h);
    lo = f16x2_pack(f0 - bk.x, f1 - bk.y);
}

__device__ __forceinline__ void cp16(uint32_t sdst, const void* gsrc) {
    asm volatile("cp.async.cg.shared.global [%0], [%1], 16;" :: "r"(sdst), "l"(gsrc));
}
__device__ __forceinline__ void cp_commit() {
    asm volatile("cp.async.commit_group;" ::: "memory");
}
template <int N_>
__device__ __forceinline__ void cp_wait() {
    asm volatile("cp.async.wait_group %0;" :: "n"(N_) : "memory");
}

// ===========================================================================
// Pre-pass 1: fp32 [R][C] -> fp16 hi/lo planes [R][C/2]
// ===========================================================================
__global__ __launch_bounds__(256) void split_pairs(
    const float* __restrict__ in, uint32_t* __restrict__ hi,
    uint32_t* __restrict__ lo, int n_pairs)
{
    int i = blockIdx.x * 256 + threadIdx.x;
    if (i < n_pairs) {
        float2 v = reinterpret_cast<const float2*>(in)[i];
        uint32_t h, l;
        f16x3_split(v.x, v.y, h, l);
        hi[i] = h; lo[i] = l;
    }
}

// ===========================================================================
// Pre-pass 2: W [K][N] fp32 -> single rounded fp16 transposed plane [N][K/2]
// ===========================================================================
__global__ __launch_bounds__(256) void round_trans(
    const float* __restrict__ W, uint32_t* __restrict__ bt, int K, int N)
{
    __shared__ float s[64][65];
    const int k0 = blockIdx.y * 64, n0 = blockIdx.x * 64;
    const int tid = threadIdx.x;
#pragma unroll
    for (int i = 0; i < 16; i++) {
        int f = tid + i * 256;
        s[f >> 6][f & 63] = W[(size_t)(k0 + (f >> 6)) * N + n0 + (f & 63)];
    }
    __syncthreads();
    const int kp = tid & 31;
    const int Kp = K >> 1;
#pragma unroll
    for (int i = 0; i < 8; i++) {
        int nn = (tid >> 5) + i * 8;
        bt[(size_t)(n0 + nn) * Kp + (k0 >> 1) + kp] =
            f16x2_pack(s[2 * kp][nn], s[2 * kp + 1][nn]);
    }
}

// ===========================================================================
// fp16x2-pass GEMM: C = (Ah + Al) @ Bf^T + bias, Bf = fp16(B).
// 128x128 CTA tile, BK=32 (16 u32), 512 threads (16 warps, 4m x 4n).
// 3-stage cp.async ring, 1 barrier/tile, hoisted fragment loads.
// Stage (u32): AHI 0, ALO 2560, BF 5120 (rows stride 20). 30720 B/stage.
// write_mode: 0 = fp32 Cf, 1 = single fp16 plane Ch.
// ===========================================================================
#define G_STAGE_U32 7680
#define G_STAGE_B   (G_STAGE_U32 * 4)
#define G_SMEM_BYTES (3 * G_STAGE_B)        // 92160

__global__ __launch_bounds__(512) void gemm_f16(
    const uint32_t* __restrict__ Ahi, const uint32_t* __restrict__ Alo,
    const uint32_t* __restrict__ Bf,
    const float* __restrict__ bias,
    float* __restrict__ Cf, uint32_t* __restrict__ Ch,
    int M, int N, int K, int write_mode)
{
    extern __shared__ uint32_t s32[];
    const uint32_t sbase = smem_u32(s32);

    const int tid  = threadIdx.x;
    const int lane = tid & 31;
    const int wid  = tid >> 5;
    const int g    = lane >> 2;
    const int tg   = lane & 3;
    const int wm   = wid & 3;
    const int wn   = wid >> 2;
    const int rowA0 = blockIdx.y * 128;
    const int colB0 = blockIdx.x * 128;
    const int Kp   = K >> 1;

    const int lrow = tid >> 2;
    const int lj   = tid & 3;
    const uint32_t s_off = (uint32_t)(lrow * 20 + lj * 4) * 4;
    const uint32_t sA_hi = sbase + s_off;
    const uint32_t sA_lo = sbase + 2560 * 4 + s_off;
    const uint32_t sB_f  = sbase + 5120 * 4 + s_off;
    const uint32_t* gA_hi = Ahi + (size_t)(rowA0 + lrow) * Kp + lj * 4;
    const uint32_t* gA_lo = Alo + (size_t)(rowA0 + lrow) * Kp + lj * 4;
    const uint32_t* gB_f  = Bf  + (size_t)(colB0 + lrow) * Kp + lj * 4;

    const uint32_t a_lane = (uint32_t)((wm * 32 + (lane & 15)) * 80 + ((lane >> 4) << 4));
    const uint32_t b_lane = (uint32_t)((wn * 32 + (lane & 15)) * 80 + ((lane >> 4) << 4));
    const uint32_t AHIa = sbase + a_lane;
    const uint32_t ALOa = sbase + 2560 * 4 + a_lane;
    const uint32_t BFa  = sbase + 5120 * 4 + b_lane;

    float acc[2][4][4];
#pragma unroll
    for (int mt = 0; mt < 2; mt++)
#pragma unroll
        for (int nt = 0; nt < 4; nt++)
#pragma unroll
            for (int i = 0; i < 4; i++) acc[mt][nt][i] = 0.f;

    const int T = K / 32;

    // prologue: stages 0, 1
#pragma unroll
    for (int p = 0; p < 2; p++) {
        const uint32_t st = (uint32_t)p * G_STAGE_B;
        const int ko = p * 16;
        cp16(sA_hi + st, gA_hi + ko); cp16(sA_lo + st, gA_lo + ko);
        cp16(sB_f + st, gB_f + ko);
        cp_commit();
    }

    int s_rd = 0, s_wr = 2;
    for (int t = 0; t < T; t++) {
        cp_wait<1>();
        __syncthreads();

        if (t + 2 < T) {
            const uint32_t st = (uint32_t)s_wr * G_STAGE_B;
            const int ko = (t + 2) * 16;
            cp16(sA_hi + st, gA_hi + ko); cp16(sA_lo + st, gA_lo + ko);
            cp16(sB_f + st, gB_f + ko);
        }
        cp_commit();

        const uint32_t stg = (uint32_t)s_rd * G_STAGE_B;

        // hoist all fragment loads (both ksteps)
        uint32_t aL[2][2][4], aH[2][2][4], bfr[2][4][2], q[4];
#pragma unroll
        for (int ks = 0; ks < 2; ks++) {
            const uint32_t ko = stg + ks * 32;
            ldmx4(aL[ks][0], ALOa + ko);
            ldmx4(aL[ks][1], ALOa + ko + 1280);
            ldmx4(aH[ks][0], AHIa + ko);
            ldmx4(aH[ks][1], AHIa + ko + 1280);
            ldmx4(q, BFa + ko);
            bfr[ks][0][0] = q[0]; bfr[ks][1][0] = q[1];
            bfr[ks][0][1] = q[2]; bfr[ks][1][1] = q[3];
            ldmx4(q, BFa + ko + 1280);
            bfr[ks][2][0] = q[0]; bfr[ks][3][0] = q[1];
            bfr[ks][2][1] = q[2]; bfr[ks][3][1] = q[3];
        }

        // 32 MMAs
#pragma unroll
        for (int ks = 0; ks < 2; ks++) {
#pragma unroll
            for (int mt = 0; mt < 2; mt++)
#pragma unroll
                for (int nt = 0; nt < 4; nt++)
                    mma_f16(acc[mt][nt], aL[ks][mt], bfr[ks][nt]);
#pragma unroll
            for (int mt = 0; mt < 2; mt++)
#pragma unroll
                for (int nt = 0; nt < 4; nt++)
                    mma_f16(acc[mt][nt], aH[ks][mt], bfr[ks][nt]);
        }

        s_rd = (s_rd == 2) ? 0 : s_rd + 1;
        s_wr = (s_wr == 2) ? 0 : s_wr + 1;
    }

    // ---- epilogue ----
    const int Np = N >> 1;
#pragma unroll
    for (int mt = 0; mt < 2; mt++) {
        const int row = rowA0 + wm * 32 + mt * 16 + g;
#pragma unroll
        for (int nt = 0; nt < 4; nt++) {
            const int col = colB0 + wn * 32 + nt * 8 + 2 * tg;
            const float b0v = bias[col], b1v = bias[col + 1];
            const float c0 = acc[mt][nt][0] + b0v, c1 = acc[mt][nt][1] + b1v;
            const float c2 = acc[mt][nt][2] + b0v, c3 = acc[mt][nt][3] + b1v;
            if (write_mode) {
                Ch[(size_t)row * Np + (col >> 1)]       = f16x2_pack(c0, c1);
                Ch[(size_t)(row + 8) * Np + (col >> 1)] = f16x2_pack(c2, c3);
            } else {
                *reinterpret_cast<float2*>(&Cf[(size_t)row * N + col]) =
                    make_float2(c0, c1);
                *reinterpret_cast<float2*>(&Cf[(size_t)(row + 8) * N + col]) =
                    make_float2(c2, c3);
            }
        }
    }
}

// ===========================================================================
// Flash attention, fp16, qkv single plane input.
// QK^T: single pass (softmax crushes score error). PV: P split / V rounded.
// SMEM (u32): QF 0 (4608), K/V stages at 4608 + s*2304: KF +0, VF +1152.
// Rows stride 36 u32 (144 B). Total 36864 B -> 3 CTAs/SM.
// Epilogue writes attn fp16 hi/lo planes for gemm2's split-A operand.
// ===========================================================================
#define AT_STAGE_U32 2304
#define AT_SMEM_BYTES 36864

__global__ __launch_bounds__(128, 3) void flash_attn_f16(
    const uint32_t* __restrict__ gq,
    uint32_t* __restrict__ ahi, uint32_t* __restrict__ alo)
{
    extern __shared__ uint32_t s32[];
    const uint32_t sb = smem_u32(s32);
    uint32_t* QF = s32;

    const int t    = threadIdx.x;
    const int lane = t & 31;
    const int w    = t >> 5;
    const int g    = lane >> 2;
    const int tg   = lane & 3;
    const int bh   = blockIdx.y;
    const int b    = bh >> 4;
    const int h    = bh & 15;
    const int q0   = blockIdx.x * 128;
    const size_t brow = (size_t)b * S_LEN;
    const int qb   = w * 32;

    const uint32_t QFa = sb;
    const uint32_t q_lane = (uint32_t)((qb + (lane & 15)) * 144 + ((lane >> 4) << 4));
    const uint32_t k_lane = (uint32_t)((lane & 15) * 144 + ((lane >> 4) << 4));
    const uint32_t v_lane = (uint32_t)(((lane & 7) + ((lane >> 3) & 1) * 8) * 144
                                       + ((lane >> 4) << 4));

    const int pr = t >> 3;
    const int pc = t & 7;

    // ---- copy Q plane [128 x 32 u32] (once) ----
#pragma unroll
    for (int i = 0; i < 8; i++) {
        int f = t + i * 128;
        int r = f >> 3, c = f & 7;
        *reinterpret_cast<uint4*>(QF + r * 36 + c * 4) =
            *reinterpret_cast<const uint4*>(gq + (brow + q0 + r) * 1536 + h * 32 + c * 4);
    }

    float oacc[2][8][4];
#pragma unroll
    for (int mt = 0; mt < 2; mt++)
#pragma unroll
        for (int nt = 0; nt < 8; nt++)
#pragma unroll
            for (int i = 0; i < 4; i++) oacc[mt][nt][i] = 0.f;
    float lrow[2][2] = {{0.f, 0.f}, {0.f, 0.f}};

    // ---- prefetch K/V tile 0 into stage 0 ----
#pragma unroll
    for (int i = 0; i < 2; i++) {
        int r = pr + i * 16;
        const size_t srcK = (brow + r) * 1536 + 512 + h * 32 + pc * 4;
        uint32_t d = sb + (4608u + (uint32_t)(r * 36 + pc * 4)) * 4;
        cp16(d,            gq + srcK);          // K
        cp16(d + 1152 * 4, gq + srcK + 512);    // V
    }
    cp_commit();

    for (int kt = 0; kt < S_LEN / 32; kt++) {
        if (kt + 1 < S_LEN / 32) {
            const uint32_t stg_w = 4608u + (uint32_t)((kt + 1) & 1) * AT_STAGE_U32;
#pragma unroll
            for (int i = 0; i < 2; i++) {
                int r = pr + i * 16;
                const size_t srcK = (brow + (kt + 1) * 32 + r) * 1536 + 512
                                    + h * 32 + pc * 4;
                uint32_t d = sb + (stg_w + (uint32_t)(r * 36 + pc * 4)) * 4;
                cp16(d,            gq + srcK);
                cp16(d + 1152 * 4, gq + srcK + 512);
            }
            cp_commit();
            cp_wait<1>();
        } else {
            cp_wait<0>();
        }
        __syncthreads();

        const uint32_t stg = 4608u + (uint32_t)(kt & 1) * AT_STAGE_U32;
        const uint32_t KFa = sb + stg * 4 + k_lane;
        const uint32_t VFa = sb + (stg + 1152) * 4 + v_lane;

        // ---- S = Q K^T : single fp16 pass, 4 ksteps ----
        float sacc[2][4][4];
#pragma unroll
        for (int mt = 0; mt < 2; mt++)
#pragma unroll
            for (int nt = 0; nt < 4; nt++)
#pragma unroll
                for (int i = 0; i < 4; i++) sacc[mt][nt][i] = 0.f;

#pragma unroll
        for (int ks = 0; ks < 4; ks++) {
            const uint32_t ko = ks * 32;
            uint32_t qf[2][4], bfr[4][2], q[4];
            ldmx4(qf[0], QFa + q_lane + ko);
            ldmx4(qf[1], QFa + q_lane + ko + 2304);
            ldmx4(q, KFa + ko);
            bfr[0][0] = q[0]; bfr[1][0] = q[1]; bfr[0][1] = q[2]; bfr[1][1] = q[3];
            ldmx4(q, KFa + ko + 2304);
            bfr[2][0] = q[0]; bfr[3][0] = q[1]; bfr[2][1] = q[2]; bfr[3][1] = q[3];
#pragma unroll
            for (int mt = 0; mt < 2; mt++)
#pragma unroll
                for (int nt = 0; nt < 4; nt++)
                    mma_f16(sacc[mt][nt], qf[mt], bfr[nt]);
        }

        // ---- P = exp(S/8): accumulate l, split into fp16 hi/lo A-frags ----
        uint32_t phi[2][4][2], plo[2][4][2];
#pragma unroll
        for (int mt = 0; mt < 2; mt++)
#pragma unroll
            for (int nt = 0; nt < 4; nt++) {
                float p0 = __expf(0.125f * sacc[mt][nt][0]);
                float p1 = __expf(0.125f * sacc[mt][nt][1]);
                float p2 = __expf(0.125f * sacc[mt][nt][2]);
                float p3 = __expf(0.125f * sacc[mt][nt][3]);
                lrow[mt][0] += p0 + p1;
                lrow[mt][1] += p2 + p3;
                f16x3_split(p0, p1, phi[mt][nt][0], plo[mt][nt][0]);
                f16x3_split(p2, p3, phi[mt][nt][1], plo[mt][nt][1]);
            }

        // ---- O += P V : P split / V rounded, 2 passes ----
#pragma unroll
        for (int s = 0; s < 2; s++) {
            uint32_t vfr[8][2], ah[2][4], al[2][4], q[4];
#pragma unroll
            for (int mt = 0; mt < 2; mt++) {
                ah[mt][0] = phi[mt][2 * s][0];     ah[mt][1] = phi[mt][2 * s][1];
                ah[mt][2] = phi[mt][2 * s + 1][0]; ah[mt][3] = phi[mt][2 * s + 1][1];
                al[mt][0] = plo[mt][2 * s][0];     al[mt][1] = plo[mt][2 * s][1];
                al[mt][2] = plo[mt][2 * s + 1][0]; al[mt][3] = plo[mt][2 * s + 1][1];
            }
#pragma unroll
            for (int nb = 0; nb < 4; nb++) {
                ldmx4t(q, VFa + s * 2304 + nb * 32);
                vfr[2 * nb][0] = q[0];     vfr[2 * nb][1] = q[1];
                vfr[2 * nb + 1][0] = q[2]; vfr[2 * nb + 1][1] = q[3];
            }
#pragma unroll
            for (int mt = 0; mt < 2; mt++)
#pragma unroll
                for (int nt = 0; nt < 8; nt++)
                    mma_f16(oacc[mt][nt], al[mt], vfr[nt]);
#pragma unroll
            for (int mt = 0; mt < 2; mt++)
#pragma unroll
                for (int nt = 0; nt < 8; nt++)
                    mma_f16(oacc[mt][nt], ah[mt], vfr[nt]);
        }
        __syncthreads();
    }

    // ---- finalize l ----
#pragma unroll
    for (int mt = 0; mt < 2; mt++)
#pragma unroll
        for (int hf = 0; hf < 2; hf++) {
            float v = lrow[mt][hf];
            v += __shfl_xor_sync(0xffffffff, v, 1);
            v += __shfl_xor_sync(0xffffffff, v, 2);
            lrow[mt][hf] = 1.0f / v;
        }

    // ---- write O planes (fp16 split) ----
#pragma unroll
    for (int mt = 0; mt < 2; mt++) {
        const size_t r0 = brow + q0 + qb + mt * 16 + g;
#pragma unroll
        for (int nt = 0; nt < 8; nt++) {
            const int cp = h * 32 + nt * 4 + tg;
            uint32_t hh, ll;
            f16x3_split(oacc[mt][nt][0] * lrow[mt][0],
                        oacc[mt][nt][1] * lrow[mt][0], hh, ll);
            ahi[r0 * 512 + cp] = hh; alo[r0 * 512 + cp] = ll;
            f16x3_split(oacc[mt][nt][2] * lrow[mt][1],
                        oacc[mt][nt][3] * lrow[mt][1], hh, ll);
            ahi[(r0 + 8) * 512 + cp] = hh; alo[(r0 + 8) * 512 + cp] = ll;
        }
    }
}

// ===========================================================================
extern "C" void kernel_launch(void* const* d_in, const int* in_sizes, int n_in,
                              void* d_out, int out_size)
{
    const float* x     = (const float*)d_in[0];
    const float* W_in  = (const float*)d_in[1];
    const float* b_in  = (const float*)d_in[2];
    const float* W_out = (const float*)d_in[3];
    const float* b_out = (const float*)d_in[4];
    float* out = (float*)d_out;

    uint32_t *xh, *xl, *wi, *wo, *qv, *ah, *al;
    cudaGetSymbolAddress((void**)&xh, g_x_hi);
    cudaGetSymbolAddress((void**)&xl, g_x_lo);
    cudaGetSymbolAddress((void**)&wi, g_win);
    cudaGetSymbolAddress((void**)&wo, g_wout);
    cudaGetSymbolAddress((void**)&qv, g_qkv);
    cudaGetSymbolAddress((void**)&ah, g_attn_hi);
    cudaGetSymbolAddress((void**)&al, g_attn_lo);

    const int M = M_TOK;
    const int D = D_EMBED;

    cudaFuncSetAttribute(gemm_f16,
                         cudaFuncAttributeMaxDynamicSharedMemorySize, G_SMEM_BYTES);
    cudaFuncSetAttribute(flash_attn_f16,
                         cudaFuncAttributeMaxDynamicSharedMemorySize, AT_SMEM_BYTES);

    // 0) pre-split / round inputs
    split_pairs<<<(M * D / 2 + 255) / 256, 256>>>(x, xh, xl, M * D / 2);
    round_trans<<<dim3(3 * D / 64, D / 64), 256>>>(W_in, wi, D, 3 * D);
    round_trans<<<dim3(D / 64, D / 64), 256>>>(W_out, wo, D, D);

    // 1) QKV projection -> qkv fp16 plane
    {
        dim3 grid(3 * D / 128, M / 128);
        gemm_f16<<<grid, 512, G_SMEM_BYTES>>>(
            xh, xl, wi, b_in, nullptr, qv, M, 3 * D, D, 1);
    }
    // 2) attention -> attn fp16 hi/lo planes
    {
        dim3 grid(S_LEN / 128, BATCH * NHEADS);
        flash_attn_f16<<<grid, 128, AT_SMEM_BYTES>>>(qv, ah, al);
    }
    // 3) output projection -> fp32 out
    {
        dim3 grid(D / 128, M / 128);
        gemm_f16<<<grid, 512, G_SMEM_BYTES>>>(
            ah, al, wo, b_out, out, nullptr, M, D, D, 0);
    }
}